// round 15
// baseline (speedup 1.0000x reference)
#include <cuda_runtime.h>

// VectorQuantization: N=32768 rows of D=64 vs K=1024 codes.
// out = [quantized (N*D) | indices as float (N) | commitment_loss (1)]
//
// R15: occupancy push with a no-spill tile. 4 rows x 12 codes/thread
// (48 f32x2 accs = 96 regs) under __launch_bounds__(128,3) -> 3 blocks/SM,
// 12 warps (3/SMSP vs R10's 2). Mix preserved (48 FFMA2 : 8 LDS per dp).
// K padded to 1056 = 22 splits x 48 codes; pad codes get wnorm=+inf (never
// selected). Rounding-critical sequences identical to all passing rounds.

#define NROWS 32768
#define D     64
#define RB    128                   // rows per block
#define KTOT  1024
#define KPB   48                    // codes per block (one tile)
#define SPL   22                    // ceil(1024/48) -> padded K = 1056
#define TPB   128
#define NBLKM ((NROWS / RB) * SPL)  // 5632
#define EPB   64
#define NEPI  (NROWS / EPB)         // 512

#define SX_BYTES  (32 * RB * 8)     // 32768: x d-pairs [dp][row]
#define SWD_BYTES (32 * KPB * 8)    // 12288: w d-pairs [dp][code]
#define SXN_OFF   (SX_BYTES + SWD_BYTES)
#define SWN_OFF   (SXN_OFF + RB * 4)
#define SMEM_ALL  (SWN_OFF + KPB * 4)   // 45760 B -> 3 blocks/SM fits

__device__ float g_best[SPL * NROWS];
__device__ int   g_bidx[SPL * NROWS];
__device__ float g_partial[NEPI];

static __device__ __forceinline__ unsigned long long ffma2(unsigned long long a,
                                                           unsigned long long b,
                                                           unsigned long long c) {
    unsigned long long d;
    asm("fma.rn.f32x2 %0, %1, %2, %3;" : "=l"(d) : "l"(a), "l"(b), "l"(c));
    return d;
}
static __device__ __forceinline__ unsigned long long pack2(float lo, float hi) {
    unsigned long long r;
    asm("mov.b64 %0, {%1, %2};" : "=l"(r) : "f"(lo), "f"(hi));
    return r;
}
static __device__ __forceinline__ void unpack2(unsigned long long v, float& lo, float& hi) {
    asm("mov.b64 {%0, %1}, %2;" : "=f"(lo), "=f"(hi) : "l"(v));
}

// ---- Kernel A: 128-row x 48-code block -------------------------------------
__global__ void __launch_bounds__(TPB, 3) vq_main(const float* __restrict__ x,
                                                  const float* __restrict__ w) {
    extern __shared__ __align__(16) char smem_raw[];
    unsigned long long* sx  = reinterpret_cast<unsigned long long*>(smem_raw);             // [dp][128 rows]
    unsigned long long* swd = reinterpret_cast<unsigned long long*>(smem_raw + SX_BYTES);  // [dp][48 codes]
    float* sxn = reinterpret_cast<float*>(smem_raw + SXN_OFF);   // [RB]
    float* swn = reinterpret_cast<float*>(smem_raw + SWN_OFF);   // [KPB]
    // merge buffers overlay swd after final sync (4KB <= 12KB)
    float* m_b = reinterpret_cast<float*>(smem_raw + SX_BYTES);             // [4*RB]
    int*   m_i = reinterpret_cast<int*>(smem_raw + SX_BYTES + 4 * RB * 4);  // [4*RB]

    const int tid   = threadIdx.x;
    const int lane  = tid & 31;
    const int warp  = tid >> 5;                  // 0..3: codes [12w, 12w+12)
    const unsigned bid = blockIdx.x;
    const int split = bid % SPL;
    const int row0  = (bid / SPL) * RB;
    const int k0    = split * KPB;

    // ---- stage x row tid (all threads); w code k0+tid (tid<48); one sync ----
    {
        const float4* xr = reinterpret_cast<const float4*>(x + (size_t)(row0 + tid) * D);
        float sX = 0.f;
#pragma unroll
        for (int i = 0; i < 16; i++) {
            float4 v = xr[i];
            sX = __fadd_rn(sX, __fmul_rn(v.x, v.x));
            sX = __fadd_rn(sX, __fmul_rn(v.y, v.y));
            sX = __fadd_rn(sX, __fmul_rn(v.z, v.z));
            sX = __fadd_rn(sX, __fmul_rn(v.w, v.w));
            sx[(2 * i) * RB + tid]     = pack2(v.x, v.y);
            sx[(2 * i + 1) * RB + tid] = pack2(v.z, v.w);
        }
        sxn[tid] = sX;
    }
    if (tid < KPB) {
        const int kidx = k0 + tid;
        if (kidx < KTOT) {
            const float4* wrp = reinterpret_cast<const float4*>(w + (size_t)kidx * D);
            float sW = 0.f;
#pragma unroll
            for (int i = 0; i < 16; i++) {
                float4 u = wrp[i];
                sW = __fadd_rn(sW, __fmul_rn(u.x, u.x));
                sW = __fadd_rn(sW, __fmul_rn(u.y, u.y));
                sW = __fadd_rn(sW, __fmul_rn(u.z, u.z));
                sW = __fadd_rn(sW, __fmul_rn(u.w, u.w));
                swd[(2 * i) * KPB + tid]     = pack2(u.x, u.y);
                swd[(2 * i + 1) * KPB + tid] = pack2(u.z, u.w);
            }
            swn[tid] = sW;
        } else {
            // padded code: zero data, +inf norm -> distance +inf, never wins
#pragma unroll
            for (int i = 0; i < 32; i++) swd[i * KPB + tid] = 0ull;
            swn[tid] = __int_as_float(0x7f800000);
        }
    }
    __syncthreads();

    // thread's 4 rows: 2*lane, 2*lane+1, 64+2*lane, 65+2*lane
    const int rlA = 2 * lane;
    const int rlB = 64 + 2 * lane;
    const float xnr[4] = {sxn[rlA], sxn[rlA + 1], sxn[rlB], sxn[rlB + 1]};

    float bb[4];
    int   bi[4];
#pragma unroll
    for (int r = 0; r < 4; r++) { bb[r] = 3.4e38f; bi[r] = k0; }

    const ulonglong2* sxu = reinterpret_cast<const ulonglong2*>(sx);   // [dp][64 row-pairs]
    const ulonglong2* swu = reinterpret_cast<const ulonglong2*>(swd);  // [dp][24 code-pairs]

    unsigned long long acc[4][12];
#pragma unroll
    for (int r = 0; r < 4; r++)
#pragma unroll
        for (int c = 0; c < 12; c++) acc[r][c] = 0ull;

#pragma unroll 4
    for (int dp = 0; dp < 32; dp++) {
        // x: 2 full-spread LDS.128 (lane-contiguous 16B)
        ulonglong2 xa = sxu[dp * 64 + lane];        // rows 2L, 2L+1
        ulonglong2 xb = sxu[dp * 64 + 32 + lane];   // rows 64+2L, 65+2L
        const unsigned long long xv[4] = {xa.x, xa.y, xb.x, xb.y};
        // w: 6 broadcast LDS.128 (all lanes same addr), 12 codes
#pragma unroll
        for (int j = 0; j < 6; j++) {
            ulonglong2 wp = swu[dp * 24 + warp * 6 + j];   // codes 12w+2j, +1
#pragma unroll
            for (int r = 0; r < 4; r++)
                acc[r][2 * j]     = ffma2(xv[r], wp.x, acc[r][2 * j]);
#pragma unroll
            for (int r = 0; r < 4; r++)
                acc[r][2 * j + 1] = ffma2(xv[r], wp.y, acc[r][2 * j + 1]);
        }
    }

    // ---- tail: dists + per-thread argmin, codes ascending ----
#pragma unroll
    for (int c = 0; c < 12; c++) {
        const int cl = warp * 12 + c;
        const float wn = swn[cl];
        const int cglob = k0 + cl;
#pragma unroll
        for (int r = 0; r < 4; r++) {
            float lo, hi;
            unpack2(acc[r][c], lo, hi);
            float dot = __fadd_rn(lo, hi);
            // Reference rounding: (||x||^2 + ||e||^2) - (2.0 * dot).
            float dist = __fsub_rn(__fadd_rn(xnr[r], wn), __fmul_rn(2.0f, dot));
            if (dist < bb[r]) { bb[r] = dist; bi[r] = cglob; }
        }
    }

    // ---- cross-warp merge (warps own disjoint code chunks, same rows) ----
    __syncthreads();  // tails done; safe to overlay swd region
    m_b[warp * RB + rlA]     = bb[0];  m_i[warp * RB + rlA]     = bi[0];
    m_b[warp * RB + rlA + 1] = bb[1];  m_i[warp * RB + rlA + 1] = bi[1];
    m_b[warp * RB + rlB]     = bb[2];  m_i[warp * RB + rlB]     = bi[2];
    m_b[warp * RB + rlB + 1] = bb[3];  m_i[warp * RB + rlB + 1] = bi[3];
    __syncthreads();
    {
        float B = m_b[tid];
        int   I = m_i[tid];
#pragma unroll
        for (int ww = 1; ww < 4; ww++) {
            float b2 = m_b[ww * RB + tid];
            int   i2 = m_i[ww * RB + tid];
            if (b2 < B || (b2 == B && i2 < I)) { B = b2; I = i2; }  // lowest idx ties
        }
        g_best[split * NROWS + row0 + tid] = B;
        g_bidx[split * NROWS + row0 + tid] = I;
    }
}

// ---- Kernel B: reduce splits, gather, STE output, loss partials ------------
__global__ void __launch_bounds__(EPB) vq_epi(const float* __restrict__ x,
                                              const float* __restrict__ w,
                                              float* __restrict__ out_q,
                                              float* __restrict__ out_idx,
                                              int has_idx) {
    __shared__ float s_red[EPB];
    const int tid = threadIdx.x;
    const int row = blockIdx.x * EPB + tid;

    float best = g_best[row];
    int bidx = g_bidx[row];
#pragma unroll
    for (int s = 1; s < SPL; s++) {
        float b = g_best[s * NROWS + row];
        int   i = g_bidx[s * NROWS + row];
        if (b < best) { best = b; bidx = i; }  // strict <: earlier split wins ties
    }

    const float4* wb   = reinterpret_cast<const float4*>(w + (size_t)bidx * D);
    const float4* xrow = reinterpret_cast<const float4*>(x + (size_t)row * D);
    float4* oq = reinterpret_cast<float4*>(out_q + (size_t)row * D);
    float lsum = 0.f;
#pragma unroll
    for (int i = 0; i < 16; i++) {
        float4 wv = wb[i];
        float4 xv = xrow[i];
        float4 dv, ov;
        dv.x = __fsub_rn(wv.x, xv.x);
        dv.y = __fsub_rn(wv.y, xv.y);
        dv.z = __fsub_rn(wv.z, xv.z);
        dv.w = __fsub_rn(wv.w, xv.w);
        ov.x = __fadd_rn(xv.x, dv.x);   // inputs + (quantized - inputs)
        ov.y = __fadd_rn(xv.y, dv.y);
        ov.z = __fadd_rn(xv.z, dv.z);
        ov.w = __fadd_rn(xv.w, dv.w);
        lsum += dv.x * dv.x + dv.y * dv.y + dv.z * dv.z + dv.w * dv.w;
        oq[i] = ov;
    }
    if (has_idx) out_idx[row] = (float)bidx;

    s_red[tid] = lsum;
    __syncthreads();
#pragma unroll
    for (int s = EPB / 2; s > 0; s >>= 1) {
        if (tid < s) s_red[tid] = __fadd_rn(s_red[tid], s_red[tid + s]);
        __syncthreads();
    }
    if (tid == 0) g_partial[blockIdx.x] = s_red[0];
}

// ---- Kernel C: final deterministic reduction -> commitment loss ------------
__global__ void vq_final(float* __restrict__ out_loss) {
    __shared__ float s[256];
    int tid = threadIdx.x;  // 256 threads over 512 partials
    s[tid] = __fadd_rn(g_partial[tid], g_partial[tid + 256]);
    __syncthreads();
    for (int st = 128; st > 0; st >>= 1) {
        if (tid < st) s[tid] = __fadd_rn(s[tid], s[tid + st]);
        __syncthreads();
    }
    if (tid == 0) {
        float mean = s[0] / 2097152.0f;  // exact: power-of-two divisor
        *out_loss = 0.25f * (mean + mean);
    }
}

extern "C" void kernel_launch(void* const* d_in, const int* in_sizes, int n_in,
                              void* d_out, int out_size) {
    const float* x;
    const float* w;
    if (n_in >= 2 && in_sizes[0] == KTOT * D && in_sizes[1] != KTOT * D) {
        w = (const float*)d_in[0];
        x = (const float*)d_in[1];
    } else {
        x = (const float*)d_in[0];
        w = (const float*)d_in[1];
    }

    float* out = (float*)d_out;
    const long ND = (long)NROWS * D;
    if (out_size < ND) return;

    int has_idx  = out_size >= ND + NROWS;
    int has_loss = out_size >= ND + NROWS + 1;

    cudaFuncSetAttribute(vq_main, cudaFuncAttributeMaxDynamicSharedMemorySize, SMEM_ALL);
    vq_main<<<NBLKM, TPB, SMEM_ALL>>>(x, w);
    vq_epi<<<NEPI, EPB>>>(x, w, out, out + ND, has_idx);
    if (has_loss) vq_final<<<1, 256>>>(out + ND + NROWS);
}

// round 16
// speedup vs baseline: 1.2193x; 1.2193x over previous
#include <cuda_runtime.h>

// VectorQuantization: N=32768 rows of D=64 vs K=1024 codes.
// out = [quantized (N*D) | indices as float (N) | commitment_loss (1)]
//
// R16: single fused kernel. Main loop = R10/R13 verbatim (best measured:
// 113us). Epilogue fused via last-block-done: 8th block per row-group merges
// splits (fixed order -> deterministic), gathers, writes STE output + loss
// partial using x STILL IN ITS SMEM; a second counter elects the loss
// reducer. Counters self-reset for graph replay. Rounding-critical
// sequences identical to all passing rounds (rel_err 1.19e-7).

#define NROWS 32768
#define D     64
#define RB    128                   // rows per block
#define CBT   64                    // codes per compute tile
#define SPL   8                     // K splits
#define KTOT  1024
#define KPB   (KTOT / SPL)          // 128 codes per block (2 tiles, both staged)
#define TILES (KPB / CBT)           // 2
#define TPB   128
#define NRG   (NROWS / RB)          // 256 row-groups
#define NBLKM (NRG * SPL)           // 2048

#define SX_BYTES  (32 * RB * 8)     // 32768: x d-pairs [dp][row]
#define SWD_BYTES (32 * KPB * 8)    // 32768: w d-pairs [dp][code]
#define SXN_OFF   (SX_BYTES + SWD_BYTES)
#define SWN_OFF   (SXN_OFF + RB * 4)
#define SMEM_ALL  (SWN_OFF + KPB * 4)

__device__ float g_best[SPL * NROWS];
__device__ int   g_bidx[SPL * NROWS];
__device__ float g_partial[NRG];
__device__ int   g_cnt[NRG];        // zero-init; reset after use each launch
__device__ int   g_cnt2;            // zero-init; reset after use each launch

static __device__ __forceinline__ unsigned long long ffma2(unsigned long long a,
                                                           unsigned long long b,
                                                           unsigned long long c) {
    unsigned long long d;
    asm("fma.rn.f32x2 %0, %1, %2, %3;" : "=l"(d) : "l"(a), "l"(b), "l"(c));
    return d;
}
static __device__ __forceinline__ unsigned long long pack2(float lo, float hi) {
    unsigned long long r;
    asm("mov.b64 %0, {%1, %2};" : "=l"(r) : "f"(lo), "f"(hi));
    return r;
}
static __device__ __forceinline__ void unpack2(unsigned long long v, float& lo, float& hi) {
    asm("mov.b64 {%0, %1}, %2;" : "=f"(lo), "=f"(hi) : "l"(v));
}

// ---- Fused kernel: 128-row x 128-code block + last-block epilogue ----------
__global__ void __launch_bounds__(TPB, 2) vq_fused(const float* __restrict__ x,
                                                   const float* __restrict__ w,
                                                   float* __restrict__ out_q,
                                                   float* __restrict__ out_idx,
                                                   float* __restrict__ out_loss,
                                                   int has_idx, int has_loss) {
    extern __shared__ __align__(16) char smem_raw[];
    unsigned long long* sx  = reinterpret_cast<unsigned long long*>(smem_raw);             // [dp][128 rows]
    unsigned long long* swd = reinterpret_cast<unsigned long long*>(smem_raw + SX_BYTES);  // [dp][128 codes]
    float* sxn = reinterpret_cast<float*>(smem_raw + SXN_OFF);   // [RB]
    float* swn = reinterpret_cast<float*>(smem_raw + SWN_OFF);   // [KPB]
    // merge buffers overlay swd after final sync (sx stays intact!)
    float* m_b = reinterpret_cast<float*>(smem_raw + SX_BYTES);             // [4*RB]
    int*   m_i = reinterpret_cast<int*>(smem_raw + SX_BYTES + 4 * RB * 4);  // [4*RB]

    const int tid    = threadIdx.x;
    const int lane   = tid & 31;
    const int warp   = tid >> 5;         // 0..3: code chunk warp*16 within tile
    const int split  = blockIdx.x & (SPL - 1);
    const int rowblk = blockIdx.x >> 3;
    const int row0   = rowblk * RB;
    const int k0     = split * KPB;

    // ---- stage x row tid AND w code row tid, concurrently; one sync ----
    {
        const float4* xr = reinterpret_cast<const float4*>(x + (size_t)(row0 + tid) * D);
        const float4* wrp = reinterpret_cast<const float4*>(w + (size_t)(k0 + tid) * D);
        float sX = 0.f, sW = 0.f;
#pragma unroll
        for (int i = 0; i < 16; i++) {
            float4 v = xr[i];
            sX = __fadd_rn(sX, __fmul_rn(v.x, v.x));
            sX = __fadd_rn(sX, __fmul_rn(v.y, v.y));
            sX = __fadd_rn(sX, __fmul_rn(v.z, v.z));
            sX = __fadd_rn(sX, __fmul_rn(v.w, v.w));
            sx[(2 * i) * RB + tid]     = pack2(v.x, v.y);
            sx[(2 * i + 1) * RB + tid] = pack2(v.z, v.w);
            float4 u = wrp[i];
            sW = __fadd_rn(sW, __fmul_rn(u.x, u.x));
            sW = __fadd_rn(sW, __fmul_rn(u.y, u.y));
            sW = __fadd_rn(sW, __fmul_rn(u.z, u.z));
            sW = __fadd_rn(sW, __fmul_rn(u.w, u.w));
            swd[(2 * i) * KPB + tid]     = pack2(u.x, u.y);
            swd[(2 * i + 1) * KPB + tid] = pack2(u.z, u.w);
        }
        sxn[tid] = sX;
        swn[tid] = sW;
    }
    __syncthreads();

    // thread's 4 rows: 2*lane, 2*lane+1, 64+2*lane, 65+2*lane
    const int rlA = 2 * lane;
    const int rlB = 64 + 2 * lane;
    const float xnr[4] = {sxn[rlA], sxn[rlA + 1], sxn[rlB], sxn[rlB + 1]};

    float bb[4];
    int   bi[4];
#pragma unroll
    for (int r = 0; r < 4; r++) { bb[r] = 3.4e38f; bi[r] = k0; }

    const ulonglong2* sxu = reinterpret_cast<const ulonglong2*>(sx);   // [dp][64 row-pairs]
    const ulonglong2* swu = reinterpret_cast<const ulonglong2*>(swd);  // [dp][64 code-pairs]

#pragma unroll
    for (int tile = 0; tile < TILES; tile++) {
        const int kt = k0 + tile * CBT;

        unsigned long long acc[4][16];
#pragma unroll
        for (int r = 0; r < 4; r++)
#pragma unroll
            for (int c = 0; c < 16; c++) acc[r][c] = 0ull;

#pragma unroll 8
        for (int dp = 0; dp < 32; dp++) {
            // x: 2 full-spread LDS.128 (lane-contiguous 16B, 512B distinct)
            ulonglong2 xa = sxu[dp * 64 + lane];        // rows 2L, 2L+1
            ulonglong2 xb = sxu[dp * 64 + 32 + lane];   // rows 64+2L, 65+2L
            const unsigned long long xv[4] = {xa.x, xa.y, xb.x, xb.y};
            // w: 8 broadcast LDS.128 (all lanes same addr), 16 codes
#pragma unroll
            for (int j = 0; j < 8; j++) {
                ulonglong2 wp = swu[dp * 64 + tile * 32 + warp * 8 + j];
#pragma unroll
                for (int r = 0; r < 4; r++)
                    acc[r][2 * j]     = ffma2(xv[r], wp.x, acc[r][2 * j]);
#pragma unroll
                for (int r = 0; r < 4; r++)
                    acc[r][2 * j + 1] = ffma2(xv[r], wp.y, acc[r][2 * j + 1]);
            }
        }

        // tail: dists + per-thread argmin, codes ascending
#pragma unroll
        for (int c = 0; c < 16; c++) {
            const int cl = warp * 16 + c;
            const float wn = swn[tile * CBT + cl];
            const int cglob = kt + cl;
#pragma unroll
            for (int r = 0; r < 4; r++) {
                float lo, hi;
                unpack2(acc[r][c], lo, hi);
                float dot = __fadd_rn(lo, hi);
                // Reference rounding: (||x||^2 + ||e||^2) - (2.0 * dot).
                float dist = __fsub_rn(__fadd_rn(xnr[r], wn), __fmul_rn(2.0f, dot));
                if (dist < bb[r]) { bb[r] = dist; bi[r] = cglob; }
            }
        }
    }

    // ---- cross-warp merge (warps own disjoint code chunks, same rows) ----
    __syncthreads();  // tails done; safe to overlay swd region (sx untouched)
    m_b[warp * RB + rlA]     = bb[0];  m_i[warp * RB + rlA]     = bi[0];
    m_b[warp * RB + rlA + 1] = bb[1];  m_i[warp * RB + rlA + 1] = bi[1];
    m_b[warp * RB + rlB]     = bb[2];  m_i[warp * RB + rlB]     = bi[2];
    m_b[warp * RB + rlB + 1] = bb[3];  m_i[warp * RB + rlB + 1] = bi[3];
    __syncthreads();
    {
        float B = m_b[tid];
        int   I = m_i[tid];
#pragma unroll
        for (int ww = 1; ww < 4; ww++) {
            float b2 = m_b[ww * RB + tid];
            int   i2 = m_i[ww * RB + tid];
            if (b2 < B || (b2 == B && i2 < I)) { B = b2; I = i2; }  // lowest idx ties
        }
        g_best[split * NROWS + row0 + tid] = B;
        g_bidx[split * NROWS + row0 + tid] = I;
    }

    // ==== fused epilogue: last block of this row-group does gather+STE ====
    __threadfence();
    __shared__ int s_last;
    if (tid == 0)
        s_last = (atomicAdd(&g_cnt[rowblk], 1) == SPL - 1);
    __syncthreads();
    if (!s_last) return;

    const int row = row0 + tid;
    // merge 8 split candidates, ascending split order, strict < + idx ties
    float best = g_best[row];
    int bidx = g_bidx[row];
#pragma unroll
    for (int s = 1; s < SPL; s++) {
        float b = g_best[s * NROWS + row];
        int   i = g_bidx[s * NROWS + row];
        if (b < best || (b == best && i < bidx)) { best = b; bidx = i; }
    }

    // gather winning code from gmem (L2-resident); x from OUR smem (exact bits)
    const float4* wb = reinterpret_cast<const float4*>(w + (size_t)bidx * D);
    float4* oq = reinterpret_cast<float4*>(out_q + (size_t)row * D);
    float lsum = 0.f;
#pragma unroll
    for (int i = 0; i < 16; i++) {
        float4 wv = wb[i];
        float x0, x1, x2, x3;
        unpack2(sx[(2 * i) * RB + tid],     x0, x1);
        unpack2(sx[(2 * i + 1) * RB + tid], x2, x3);
        float4 dv, ov;
        dv.x = __fsub_rn(wv.x, x0);
        dv.y = __fsub_rn(wv.y, x1);
        dv.z = __fsub_rn(wv.z, x2);
        dv.w = __fsub_rn(wv.w, x3);
        ov.x = __fadd_rn(x0, dv.x);   // inputs + (quantized - inputs)
        ov.y = __fadd_rn(x1, dv.y);
        ov.z = __fadd_rn(x2, dv.z);
        ov.w = __fadd_rn(x3, dv.w);
        lsum += dv.x * dv.x + dv.y * dv.y + dv.z * dv.z + dv.w * dv.w;
        oq[i] = ov;
    }
    if (has_idx) out_idx[row] = (float)bidx;

    // deterministic block tree-reduce of loss partials (reuse sxn)
    sxn[tid] = lsum;
    __syncthreads();
#pragma unroll
    for (int s = TPB / 2; s > 0; s >>= 1) {
        if (tid < s) sxn[tid] = __fadd_rn(sxn[tid], sxn[tid + s]);
        __syncthreads();
    }
    if (tid == 0) g_partial[rowblk] = sxn[0];

    // ==== second election: last row-group block reduces the loss ====
    __threadfence();
    __shared__ int s_last2;
    if (tid == 0) {
        g_cnt[rowblk] = 0;  // reset for next graph replay
        s_last2 = (atomicAdd(&g_cnt2, 1) == NRG - 1);
    }
    __syncthreads();
    if (!s_last2) return;

    if (has_loss) {
        // 128 threads over 256 partials, fixed-order tree -> deterministic
        sxn[tid] = __fadd_rn(g_partial[tid], g_partial[tid + TPB]);
        __syncthreads();
#pragma unroll
        for (int s = TPB / 2; s > 0; s >>= 1) {
            if (tid < s) sxn[tid] = __fadd_rn(sxn[tid], sxn[tid + s]);
            __syncthreads();
        }
        if (tid == 0) {
            float mean = sxn[0] / 2097152.0f;  // exact: power-of-two divisor
            *out_loss = 0.25f * (mean + mean);
        }
    }
    if (tid == 0) g_cnt2 = 0;  // reset for next graph replay
}

extern "C" void kernel_launch(void* const* d_in, const int* in_sizes, int n_in,
                              void* d_out, int out_size) {
    const float* x;
    const float* w;
    if (n_in >= 2 && in_sizes[0] == KTOT * D && in_sizes[1] != KTOT * D) {
        w = (const float*)d_in[0];
        x = (const float*)d_in[1];
    } else {
        x = (const float*)d_in[0];
        w = (const float*)d_in[1];
    }

    float* out = (float*)d_out;
    const long ND = (long)NROWS * D;
    if (out_size < ND) return;

    int has_idx  = out_size >= ND + NROWS;
    int has_loss = out_size >= ND + NROWS + 1;

    cudaFuncSetAttribute(vq_fused, cudaFuncAttributeMaxDynamicSharedMemorySize, SMEM_ALL);
    vq_fused<<<NBLKM, TPB, SMEM_ALL>>>(x, w, out, out + ND, out + ND + NROWS,
                                       has_idx, has_loss);
}